// round 8
// baseline (speedup 1.0000x reference)
#include <cuda_runtime.h>
#include <cstdint>

// Ragged position fill (vLLM prepare-inputs style), single fused kernel.
//   pos[t]      = nct[idx_mapping[req(t)]] + (t - qsl[req(t)])   (= base + t)
//   seq_lens[r] = nct[idx_mapping[r]] + (qsl[r+1]-qsl[r]) for r < num_reqs, else 0
// d_out = [ pos (num_tokens) | seq_lens (max_num_reqs) ]  as FLOAT32.
//
// R8 structure: blocks [0, num_reqs) do pos only (no seq logic, no
// qsl[num_reqs] load in their prologue); blocks [num_reqs, num_reqs+SEQ_BLOCKS)
// handle ALL of seq_lens. Inner store loop uses packed add.rn.f32x2 — values
// are converted to float once per thread, then incremented by +1024.0 per
// iteration (exact: all values < 2^24).

#define SEQ_BLOCKS 64

__device__ __forceinline__ unsigned long long addf32x2(unsigned long long a,
                                                       unsigned long long b) {
    unsigned long long r;
    asm("add.rn.f32x2 %0, %1, %2;" : "=l"(r) : "l"(a), "l"(b));
    return r;
}

__device__ __forceinline__ unsigned long long packf2(float lo, float hi) {
    unsigned long long r;
    asm("mov.b64 %0, {%1, %2};" : "=l"(r) : "f"(lo), "f"(hi));
    return r;
}

__global__ __launch_bounds__(256) void fused_fill_kernel(
    const int* __restrict__ idx_mapping,
    const int* __restrict__ qsl,
    const int* __restrict__ nct,
    float* __restrict__ out_base,
    int num_reqs, int max_num_reqs,
    long long out_size)
{
    const int r = blockIdx.x;

    if (r >= num_reqs) {
        // ---- seq_lens blocks: cover [0, max_num_reqs) ----
        const long long num_tokens = (long long)__ldg(&qsl[num_reqs]);
        const long long need = num_tokens + (long long)max_num_reqs;
        if (out_size != need && out_size != 4 * need) return;  // no room in d_out
        float* seq_out = out_base + num_tokens;

        const int nthreads = SEQ_BLOCKS * 256;
        int i = (r - num_reqs) * 256 + (int)threadIdx.x;
        for (; i < max_num_reqs; i += nthreads) {
            int v = 0;
            if (i < num_reqs) {
                int qlen = __ldg(&qsl[i + 1]) - __ldg(&qsl[i]);
                v = __ldg(&nct[__ldg(&idx_mapping[i])]) + qlen;
            }
            seq_out[i] = (float)v;
        }
        return;
    }

    // ---- pos blocks: one request per block ----
    const int start = __ldg(&qsl[r]);
    const int end   = __ldg(&qsl[r + 1]);
    const int im    = __ldg(&idx_mapping[r]);   // parallel with qsl loads
    if (end <= start) return;
    const int nv    = __ldg(&nct[im]);          // the one dependent load
    const int base  = nv - start;               // pos[t] = base + t

    const int aligned_s0 = (start + 3) & ~3;
    const int aligned_s1 = end & ~3;

    if (aligned_s1 > aligned_s0) {
        // head (<=3 elems)
        int t = start + (int)threadIdx.x;
        if (t < aligned_s0) out_base[t] = (float)(base + t);

        // vector body: per-thread stream of float4 stores, values advanced
        // by packed f32x2 adds (+1024.0 per component per iteration)
        const int nvec = (aligned_s1 - aligned_s0) >> 2;
        float4* vout = reinterpret_cast<float4*>(out_base + aligned_s0);

        int v = (int)threadIdx.x;
        if (v < nvec) {
            int tv0 = aligned_s0 + (v << 2) + base;
            float f0 = (float)tv0;               // single I2F per thread
            unsigned long long lo = packf2(f0, f0 + 1.0f);
            unsigned long long hi = packf2(f0 + 2.0f, f0 + 3.0f);
            const unsigned long long inc = packf2(1024.0f, 1024.0f);
            do {
                *reinterpret_cast<ulonglong2*>(vout + v) =
                    make_ulonglong2(lo, hi);
                lo = addf32x2(lo, inc);
                hi = addf32x2(hi, inc);
                v += 256;
            } while (v < nvec);
        }

        // tail (<=3 elems)
        int tt = aligned_s1 + (int)threadIdx.x;
        if (tt < end) out_base[tt] = (float)(base + tt);
    } else {
        for (int t = start + (int)threadIdx.x; t < end; t += (int)blockDim.x)
            out_base[t] = (float)(base + t);
    }
}

extern "C" void kernel_launch(void* const* d_in, const int* in_sizes, int n_in,
                              void* d_out, int out_size) {
    // stable sort of input indices by size (ascending)
    int ord[32];
    int n = n_in > 32 ? 32 : n_in;
    for (int i = 0; i < n; i++) ord[i] = i;
    for (int i = 1; i < n; i++) {
        int key = ord[i];
        int j = i - 1;
        while (j >= 0 && in_sizes[ord[j]] > in_sizes[key]) {
            ord[j + 1] = ord[j];
            j--;
        }
        ord[j + 1] = key;
    }
    // rank mapping: ord[0]=idx_mapping, ord[1]=qsl, ord[2]=num_computed_tokens
    int idx_i = ord[0];
    int qsl_i = (n > 1) ? ord[1] : ord[0];
    int nct_i = (n > 2) ? ord[2] : qsl_i;

    const int* idx_mapping = (const int*)d_in[idx_i];
    const int* qsl         = (const int*)d_in[qsl_i];
    const int* nct         = (const int*)d_in[nct_i];

    // unit: size(qsl) - size(idx) == bytes-per-element of in_sizes
    long long unit = (long long)in_sizes[qsl_i] - (long long)in_sizes[idx_i];
    if (unit <= 0) unit = 1;
    const int num_reqs     = (int)(in_sizes[idx_i] / unit);
    const int max_num_reqs = (int)(in_sizes[nct_i] / unit);

    fused_fill_kernel<<<num_reqs + SEQ_BLOCKS, 256>>>(
        idx_mapping, qsl, nct, (float*)d_out,
        num_reqs, max_num_reqs, (long long)out_size);
}